// round 9
// baseline (speedup 1.0000x reference)
#include <cuda_runtime.h>
#include <cuda_fp16.h>

#define RW 192
#define TW 182
#define TH 16          // output rows per tile
#define NP 8           // row pairs per tile
#define RH 26          // TH + 10 input rows
#define PITCH 772      // u32 words per pair-row: 192*4 + 4; 772%32==4 -> conflict-free
#define SMEM_WORDS (NP * PITCH + 160)   // pad covers phase-C tail overreads
#define NTHREADS 192
#define IMG_W 512
#define IMG_H 512
#define PLANES 96
#define NBLOCKS (3 * 32 * 96)
#define NPIX 25165824.0f

static constexpr float C1V = 0.0001f;
static constexpr float C2V = 0.0009f;

// Gaussian(sigma=1.5, k=11) weights as a constexpr function (usable in device code)
__host__ __device__ constexpr float wt(int k) {
    return (k == 0 || k == 10) ? 0.00102838f
         : (k == 1 || k == 9)  ? 0.00759876f
         : (k == 2 || k == 8)  ? 0.03600077f
         : (k == 3 || k == 7)  ? 0.10936069f
         : (k == 4 || k == 6)  ? 0.21300553f
         : (k == 5)            ? 0.26601172f
         : 0.0f;
}

__device__ float g_accum;
__device__ unsigned int g_count;

// ---- raw half2 helpers on u32 ----
__device__ __forceinline__ unsigned hfma2u(unsigned a, unsigned b, unsigned c) {
    unsigned d; asm("fma.rn.f16x2 %0,%1,%2,%3;" : "=r"(d) : "r"(a), "r"(b), "r"(c)); return d;
}
__device__ __forceinline__ unsigned hmul2u(unsigned a, unsigned b) {
    unsigned d; asm("mul.rn.f16x2 %0,%1,%2;" : "=r"(d) : "r"(a), "r"(b)); return d;
}
__device__ __forceinline__ unsigned pack_h2(float lo, float hi) {
    unsigned d;
    asm("{\n\t.reg .b16 l, h;\n\t"
        "cvt.rn.f16.f32 l, %1;\n\t"
        "cvt.rn.f16.f32 h, %2;\n\t"
        "mov.b32 %0, {l, h};\n\t}"
        : "=r"(d) : "f"(lo), "f"(hi));
    return d;
}
__device__ __forceinline__ unsigned bcast_h2(float f) {
    unsigned d; asm("cvt.rn.f16x2.f32 %0, %1, %1;" : "=r"(d) : "f"(f)); return d;
}
__device__ __forceinline__ float2 unpack_h2(unsigned u) {
    __half2 h = *reinterpret_cast<__half2*>(&u);
    return make_float2(__low2float(h), __high2float(h));
}

// Vertical blur on CENTERED inputs: ac = a - 0.5 (out-of-image -> -0.5).
// Exact identities (zero-padded conv, full-kernel weight sum = 1):
//   mu1 = blur(ac) + 0.5
//   sigma1+sigma2 = blur(ac^2+bc^2) - mu1c^2 - mu2c^2
//   sigma12       = blur(ac*bc)     - mu1c*mu2c
// Lanes of each half2 = output rows (2p, 2p+1). Weight pair (w[k], w[k-1]).
template <bool YSAFE>
__device__ __forceinline__ void vblur(const float* __restrict__ p1,
                                      const float* __restrict__ p2,
                                      unsigned* __restrict__ vw,
                                      int y0, int gx, bool xok, int tx,
                                      const unsigned (&WK)[12]) {
    unsigned acc[6][4];   // ring of 6 live pairs x 4 quantities

#pragma unroll
    for (int r = 0; r < RH; r++) {
        const int gy = y0 - 5 + r;
        float a = -0.5f, b = -0.5f;          // centered zero (out-of-image)
        if (YSAFE) {
            if (xok) {
                const int idx = gy * IMG_W + gx;
                a = __ldg(p1 + idx) - 0.5f;
                b = __ldg(p2 + idx) - 0.5f;
            }
        } else {
            const bool ok = xok && (gy >= 0) && (gy < IMG_H);
            if (ok) {
                const int idx = gy * IMG_W + gx;
                a = __ldg(p1 + idx) - 0.5f;
                b = __ldg(p2 + idx) - 0.5f;
            }
        }
        const float s = fmaf(a, a, b * b);   // ac^2 + bc^2  (<= 0.5)
        const float m = a * b;               // ac*bc        (|.| <= 0.25)
        unsigned pq[4];
        pq[0] = bcast_h2(a);
        pq[1] = bcast_h2(b);
        pq[2] = bcast_h2(s);
        pq[3] = bcast_h2(m);

#pragma unroll
        for (int p = 0; p < NP; p++) {
            const int k = r - 2 * p;            // compile-time after unroll
            if (k >= 0 && k <= 11) {
                const int j = p % 6;
                if (k == 0) {
#pragma unroll
                    for (int q = 0; q < 4; q++)
                        acc[j][q] = hmul2u(pq[q], WK[0]);   // fresh pair (lane1 *0)
                } else {
#pragma unroll
                    for (int q = 0; q < 4; q++)
                        acc[j][q] = hfma2u(pq[q], WK[k], acc[j][q]);
                }
            }
        }
        if (r >= 11 && ((r - 11) & 1) == 0) {
            const int p = (r - 11) >> 1;
            const int j = p % 6;
            uint4 w4 = make_uint4(acc[j][0], acc[j][1], acc[j][2], acc[j][3]);
            *reinterpret_cast<uint4*>(vw + p * PITCH + tx * 4) = w4;
        }
    }
}

__global__ void __launch_bounds__(NTHREADS, 4)
ssim_main(const float* __restrict__ img1, const float* __restrict__ img2,
          float* __restrict__ out) {
    extern __shared__ unsigned vw[];      // [NP][PITCH] + pad
    __shared__ float red[NTHREADS / 32];

    const int tx = threadIdx.x;
    const int plane = blockIdx.z;
    const int x0 = blockIdx.x * TW;
    const int y0 = blockIdx.y * TH;

    const float* __restrict__ p1 = img1 + (size_t)plane * (IMG_W * IMG_H);
    const float* __restrict__ p2 = img2 + (size_t)plane * (IMG_W * IMG_H);

    const int gx = x0 - 5 + tx;
    const bool xok = (gx >= 0) && (gx < IMG_W);

    // weight pairs (w[k], w[k-1]) for vertical pass; wt() is 0 out of range
    unsigned WK[12];
#pragma unroll
    for (int k = 0; k < 12; k++)
        WK[k] = pack_h2(wt(k), wt(k - 1));

    // ---------- Phase B ----------
    if (y0 >= 5 && y0 + TH + 5 <= IMG_H)
        vblur<true >(p1, p2, vw, y0, gx, xok, tx, WK);
    else
        vblur<false>(p1, p2, vw, y0, gx, xok, tx, WK);
    __syncthreads();

    // ---------- Phase C: horizontal blur + SSIM epilogue ----------
    const int rp  = tx & 7;       // pair-row 0..7 (output rows 2rp, 2rp+1)
    const int seg = tx >> 3;      // 0..23, each covers 8 output columns
    const int c0  = seg * 8;
    const int xlim = (IMG_W - x0 < TW) ? (IMG_W - x0) : TW;

    unsigned WB[6];               // broadcast weights (symmetric)
#pragma unroll
    for (int k = 0; k < 6; k++) WB[k] = bcast_h2(wt(k));

    unsigned acc[8][4];
    const unsigned* rowp = vw + rp * PITCH + c0 * 4;

#pragma unroll
    for (int i = 0; i < 18; i++) {
        // One LDS.128: 4 quantities x 2 rows of column c0+i. Tail overreads
        // (seg>=22, i large) stay in the padded allocation and feed only
        // outputs discarded by xlim.
        const uint4 w4 = *reinterpret_cast<const uint4*>(rowp + i * 4);
        unsigned pv[4] = {w4.x, w4.y, w4.z, w4.w};
#pragma unroll
        for (int xo = 0; xo < 8; xo++) {
            const int k = i - xo;
            if (k >= 0 && k <= 10) {
                const int wi = (k < 6) ? k : (10 - k);
                if (k == 0) {
#pragma unroll
                    for (int q = 0; q < 4; q++)
                        acc[xo][q] = hmul2u(pv[q], WB[0]);
                } else {
#pragma unroll
                    for (int q = 0; q < 4; q++)
                        acc[xo][q] = hfma2u(pv[q], WB[wi], acc[xo][q]);
                }
            }
        }
    }

    float lsum = 0.f;
#pragma unroll
    for (int xo = 0; xo < 8; xo++) {
        const int xout = c0 + xo;
        if (xout < xlim) {
            const float2 mu1c = unpack_h2(acc[xo][0]);
            const float2 mu2c = unpack_h2(acc[xo][1]);
            const float2 eppc = unpack_h2(acc[xo][2]);
            const float2 e12c = unpack_h2(acc[xo][3]);
#pragma unroll
            for (int h = 0; h < 2; h++) {
                const float m1c = h ? mu1c.y : mu1c.x;
                const float m2c = h ? mu2c.y : mu2c.x;
                const float epc = h ? eppc.y : eppc.x;
                const float exc = h ? e12c.y : e12c.x;
                // centered variance terms (tiny cancellation)
                const float ssum = epc - fmaf(m1c, m1c, m2c * m2c); // s1+s2
                const float s12  = exc - m1c * m2c;
                // uncentered means for luminance terms
                const float m1 = m1c + 0.5f;
                const float m2 = m2c + 0.5f;
                const float msum = fmaf(m1, m1, m2 * m2);
                const float m12  = m1 * m2;
                const float num = fmaf(2.f, m12, C1V) * fmaf(2.f, s12, C2V);
                const float den = (msum + C1V) * (ssum + C2V);
                lsum += __fdividef(num, den);
            }
        }
    }

    // ---------- reduction: shuffle -> smem -> one atomic per block ----------
#pragma unroll
    for (int off = 16; off > 0; off >>= 1)
        lsum += __shfl_xor_sync(0xffffffffu, lsum, off);
    if ((tx & 31) == 0) red[tx >> 5] = lsum;
    __syncthreads();

    if (tx == 0) {
        float bsum = 0.f;
#pragma unroll
        for (int w = 0; w < NTHREADS / 32; w++) bsum += red[w];
        atomicAdd(&g_accum, bsum);
        __threadfence();
        const unsigned int old = atomicAdd(&g_count, 1u);
        if (old == NBLOCKS - 1) {
            __threadfence();
            const float total = *(volatile float*)&g_accum;
            out[0] = 1.0f - total * (1.0f / NPIX);
            *(volatile float*)&g_accum = 0.f;
            *(volatile unsigned int*)&g_count = 0u;
        }
    }
}

extern "C" void kernel_launch(void* const* d_in, const int* in_sizes, int n_in,
                              void* d_out, int out_size) {
    const float* img1 = (const float*)d_in[0];
    const float* img2 = (const float*)d_in[1];

    const int smem = SMEM_WORDS * (int)sizeof(unsigned);   // 25,344 B
    cudaFuncSetAttribute(ssim_main, cudaFuncAttributeMaxDynamicSharedMemorySize, smem);

    dim3 grid((IMG_W + TW - 1) / TW, IMG_H / TH, PLANES);  // (3, 32, 96)
    ssim_main<<<grid, NTHREADS, smem>>>(img1, img2, (float*)d_out);
}

// round 10
// speedup vs baseline: 1.0025x; 1.0025x over previous
#include <cuda_runtime.h>
#include <cuda_fp16.h>

#define RW 192
#define TW 182
#define TH 16          // output rows per tile
#define NP 8           // row pairs per tile
#define RH 26          // TH + 10 input rows
#define PITCH 772      // u32 words per pair-row: 192*4 + 4; 772%32==4 -> conflict-free
#define SMEM_WORDS (NP * PITCH + 160)   // pad covers phase-C tail overreads
#define NTHREADS 192
#define IMG_W 512
#define IMG_H 512
#define PLANES 96
#define NBLOCKS (3 * 32 * 96)
#define NPIX 25165824.0f

static constexpr float C1V = 0.0001f;
static constexpr float C2V = 0.0009f;

// Gaussian(sigma=1.5, k=11) weights as a constexpr function (usable in device code)
__host__ __device__ constexpr float wt(int k) {
    return (k == 0 || k == 10) ? 0.00102838f
         : (k == 1 || k == 9)  ? 0.00759876f
         : (k == 2 || k == 8)  ? 0.03600077f
         : (k == 3 || k == 7)  ? 0.10936069f
         : (k == 4 || k == 6)  ? 0.21300553f
         : (k == 5)            ? 0.26601172f
         : 0.0f;
}

__device__ float g_accum;
__device__ unsigned int g_count;

// ---- raw half2 helpers on u32 ----
__device__ __forceinline__ unsigned hfma2u(unsigned a, unsigned b, unsigned c) {
    unsigned d; asm("fma.rn.f16x2 %0,%1,%2,%3;" : "=r"(d) : "r"(a), "r"(b), "r"(c)); return d;
}
__device__ __forceinline__ unsigned hmul2u(unsigned a, unsigned b) {
    unsigned d; asm("mul.rn.f16x2 %0,%1,%2;" : "=r"(d) : "r"(a), "r"(b)); return d;
}
__device__ __forceinline__ unsigned pack_h2(float lo, float hi) {
    unsigned d;
    asm("{\n\t.reg .b16 l, h;\n\t"
        "cvt.rn.f16.f32 l, %1;\n\t"
        "cvt.rn.f16.f32 h, %2;\n\t"
        "mov.b32 %0, {l, h};\n\t}"
        : "=r"(d) : "f"(lo), "f"(hi));
    return d;
}
__device__ __forceinline__ unsigned bcast_h2(float f) {
    unsigned d; asm("cvt.rn.f16x2.f32 %0, %1, %1;" : "=r"(d) : "f"(f)); return d;
}
__device__ __forceinline__ float2 unpack_h2(unsigned u) {
    __half2 h = *reinterpret_cast<__half2*>(&u);
    return make_float2(__low2float(h), __high2float(h));
}

// Vertical blur on CENTERED inputs: ac = a - 0.5 (out-of-image -> -0.5).
// Exact identities (zero-padded conv, full-kernel weight sum = 1):
//   mu1 = blur(ac) + 0.5
//   sigma1+sigma2 = blur(ac^2+bc^2) - mu1c^2 - mu2c^2
//   sigma12       = blur(ac*bc)     - mu1c*mu2c
// Lanes of each half2 = output rows (2p, 2p+1). Weight pair (w[k], w[k-1]).
template <bool YSAFE>
__device__ __forceinline__ void vblur(const float* __restrict__ p1,
                                      const float* __restrict__ p2,
                                      unsigned* __restrict__ vw,
                                      int y0, int gx, bool xok, int tx,
                                      const unsigned (&WK)[12]) {
    unsigned acc[6][4];   // ring of 6 live pairs x 4 quantities

#pragma unroll
    for (int r = 0; r < RH; r++) {
        const int gy = y0 - 5 + r;
        float a = -0.5f, b = -0.5f;          // centered zero (out-of-image)
        if (YSAFE) {
            if (xok) {
                const int idx = gy * IMG_W + gx;
                a = __ldg(p1 + idx) - 0.5f;
                b = __ldg(p2 + idx) - 0.5f;
            }
        } else {
            const bool ok = xok && (gy >= 0) && (gy < IMG_H);
            if (ok) {
                const int idx = gy * IMG_W + gx;
                a = __ldg(p1 + idx) - 0.5f;
                b = __ldg(p2 + idx) - 0.5f;
            }
        }
        const float s = fmaf(a, a, b * b);   // ac^2 + bc^2  (<= 0.5)
        const float m = a * b;               // ac*bc        (|.| <= 0.25)
        unsigned pq[4];
        pq[0] = bcast_h2(a);
        pq[1] = bcast_h2(b);
        pq[2] = bcast_h2(s);
        pq[3] = bcast_h2(m);

#pragma unroll
        for (int p = 0; p < NP; p++) {
            const int k = r - 2 * p;            // compile-time after unroll
            if (k >= 0 && k <= 11) {
                const int j = p % 6;
                if (k == 0) {
#pragma unroll
                    for (int q = 0; q < 4; q++)
                        acc[j][q] = hmul2u(pq[q], WK[0]);   // fresh pair (lane1 *0)
                } else {
#pragma unroll
                    for (int q = 0; q < 4; q++)
                        acc[j][q] = hfma2u(pq[q], WK[k], acc[j][q]);
                }
            }
        }
        if (r >= 11 && ((r - 11) & 1) == 0) {
            const int p = (r - 11) >> 1;
            const int j = p % 6;
            uint4 w4 = make_uint4(acc[j][0], acc[j][1], acc[j][2], acc[j][3]);
            *reinterpret_cast<uint4*>(vw + p * PITCH + tx * 4) = w4;
        }
    }
}

__global__ void __launch_bounds__(NTHREADS, 5)
ssim_main(const float* __restrict__ img1, const float* __restrict__ img2,
          float* __restrict__ out) {
    extern __shared__ unsigned vw[];      // [NP][PITCH] + pad
    __shared__ float red[NTHREADS / 32];

    const int tx = threadIdx.x;
    const int plane = blockIdx.z;
    const int x0 = blockIdx.x * TW;
    const int y0 = blockIdx.y * TH;

    const float* __restrict__ p1 = img1 + (size_t)plane * (IMG_W * IMG_H);
    const float* __restrict__ p2 = img2 + (size_t)plane * (IMG_W * IMG_H);

    const int gx = x0 - 5 + tx;
    const bool xok = (gx >= 0) && (gx < IMG_W);

    // weight pairs (w[k], w[k-1]) for vertical pass; wt() is 0 out of range
    unsigned WK[12];
#pragma unroll
    for (int k = 0; k < 12; k++)
        WK[k] = pack_h2(wt(k), wt(k - 1));

    // ---------- Phase B ----------
    if (y0 >= 5 && y0 + TH + 5 <= IMG_H)
        vblur<true >(p1, p2, vw, y0, gx, xok, tx, WK);
    else
        vblur<false>(p1, p2, vw, y0, gx, xok, tx, WK);
    __syncthreads();

    // ---------- Phase C: horizontal blur + SSIM epilogue ----------
    const int rp  = tx & 7;       // pair-row 0..7 (output rows 2rp, 2rp+1)
    const int seg = tx >> 3;      // 0..23, each covers 8 output columns
    const int c0  = seg * 8;
    const int xlim = (IMG_W - x0 < TW) ? (IMG_W - x0) : TW;

    unsigned WB[6];               // broadcast weights (symmetric)
#pragma unroll
    for (int k = 0; k < 6; k++) WB[k] = bcast_h2(wt(k));

    unsigned acc[8][4];
    const unsigned* rowp = vw + rp * PITCH + c0 * 4;

#pragma unroll
    for (int i = 0; i < 18; i++) {
        // One LDS.128: 4 quantities x 2 rows of column c0+i. Tail overreads
        // (seg>=22, i large) stay in the padded allocation and feed only
        // outputs discarded by xlim.
        const uint4 w4 = *reinterpret_cast<const uint4*>(rowp + i * 4);
        unsigned pv[4] = {w4.x, w4.y, w4.z, w4.w};
#pragma unroll
        for (int xo = 0; xo < 8; xo++) {
            const int k = i - xo;
            if (k >= 0 && k <= 10) {
                const int wi = (k < 6) ? k : (10 - k);
                if (k == 0) {
#pragma unroll
                    for (int q = 0; q < 4; q++)
                        acc[xo][q] = hmul2u(pv[q], WB[0]);
                } else {
#pragma unroll
                    for (int q = 0; q < 4; q++)
                        acc[xo][q] = hfma2u(pv[q], WB[wi], acc[xo][q]);
                }
            }
        }
    }

    float lsum = 0.f;
#pragma unroll
    for (int xo = 0; xo < 8; xo++) {
        const int xout = c0 + xo;
        if (xout < xlim) {
            const float2 mu1c = unpack_h2(acc[xo][0]);
            const float2 mu2c = unpack_h2(acc[xo][1]);
            const float2 eppc = unpack_h2(acc[xo][2]);
            const float2 e12c = unpack_h2(acc[xo][3]);
#pragma unroll
            for (int h = 0; h < 2; h++) {
                const float m1c = h ? mu1c.y : mu1c.x;
                const float m2c = h ? mu2c.y : mu2c.x;
                const float epc = h ? eppc.y : eppc.x;
                const float exc = h ? e12c.y : e12c.x;
                // centered variance terms (tiny cancellation)
                const float ssum = epc - fmaf(m1c, m1c, m2c * m2c); // s1+s2
                const float s12  = exc - m1c * m2c;
                // uncentered means for luminance terms
                const float m1 = m1c + 0.5f;
                const float m2 = m2c + 0.5f;
                const float msum = fmaf(m1, m1, m2 * m2);
                const float m12  = m1 * m2;
                const float num = fmaf(2.f, m12, C1V) * fmaf(2.f, s12, C2V);
                const float den = (msum + C1V) * (ssum + C2V);
                lsum += __fdividef(num, den);
            }
        }
    }

    // ---------- reduction: shuffle -> smem -> one atomic per block ----------
#pragma unroll
    for (int off = 16; off > 0; off >>= 1)
        lsum += __shfl_xor_sync(0xffffffffu, lsum, off);
    if ((tx & 31) == 0) red[tx >> 5] = lsum;
    __syncthreads();

    if (tx == 0) {
        float bsum = 0.f;
#pragma unroll
        for (int w = 0; w < NTHREADS / 32; w++) bsum += red[w];
        atomicAdd(&g_accum, bsum);
        __threadfence();
        const unsigned int old = atomicAdd(&g_count, 1u);
        if (old == NBLOCKS - 1) {
            __threadfence();
            const float total = *(volatile float*)&g_accum;
            out[0] = 1.0f - total * (1.0f / NPIX);
            *(volatile float*)&g_accum = 0.f;
            *(volatile unsigned int*)&g_count = 0u;
        }
    }
}

extern "C" void kernel_launch(void* const* d_in, const int* in_sizes, int n_in,
                              void* d_out, int out_size) {
    const float* img1 = (const float*)d_in[0];
    const float* img2 = (const float*)d_in[1];

    const int smem = SMEM_WORDS * (int)sizeof(unsigned);   // 25,344 B
    cudaFuncSetAttribute(ssim_main, cudaFuncAttributeMaxDynamicSharedMemorySize, smem);

    dim3 grid((IMG_W + TW - 1) / TW, IMG_H / TH, PLANES);  // (3, 32, 96)
    ssim_main<<<grid, NTHREADS, smem>>>(img1, img2, (float*)d_out);
}